// round 11
// baseline (speedup 1.0000x reference)
#include <cuda_runtime.h>
#include <math.h>
#include <stdint.h>

#define Bsz 64
#define Lsz 128
#define Tsz 48
#define Esz 512
#define HEsz 1024
#define Hsz 1024

// ---------------- device-global scratch ----------------
__device__ float g_h1all[(Tsz + 1) * Bsz * Hsz];   // h1 for every step (s2-owned)
__device__ float g_h2[2][Bsz * Hsz];
__device__ float g_c1[Bsz * Hsz];
__device__ float g_c2[Bsz * Hsz];
__device__ float g_o[Bsz * Hsz];
__device__ float g_at[Bsz * HEsz];
__device__ float g_eproj[(size_t)Bsz * Lsz * HEsz];  // enc @ W_att^T (precomputed, 33.5MB)
__device__ float g_part[4 * Bsz * 4 * Hsz];          // split-K partials, main stream
__device__ float g_part1[3 * Bsz * 4 * Hsz];         // split-K partials, lstm1 stream (s2)

// pre-split bf16 weights (bits as ushort)
__device__ unsigned short g_b1h[4096 * 1536], g_b1l[4096 * 1536];   // [W_ih1|W_hh1] gate-interleaved
__device__ unsigned short g_b2h[4096 * 3072], g_b2l[4096 * 3072];   // [W_ih2|W_hh2] gate-interleaved
__device__ unsigned short g_bah[1024 * 1024], g_bal[1024 * 1024];   // W_att flat (rows already K-major)
__device__ unsigned short g_bch[1024 * 2048], g_bcl[1024 * 2048];   // W_comb direct

__device__ __forceinline__ float sigmoidf_(float x) { return 1.f / (1.f + expf(-x)); }

__device__ __forceinline__ uint32_t smem_u32(const void* p) {
    uint32_t a;
    asm("{ .reg .u64 t; cvta.to.shared.u64 t, %1; cvt.u32.u64 %0, t; }" : "=r"(a) : "l"(p));
    return a;
}

// fp32 -> bf16 hi (exact truncation) + bf16 lo (rounded residual)
__device__ __forceinline__ void split4(float4 v, uint2& hi, uint2& lo) {
    uint32_t bx = __float_as_uint(v.x) & 0xFFFF0000u;
    uint32_t by = __float_as_uint(v.y) & 0xFFFF0000u;
    uint32_t bz = __float_as_uint(v.z) & 0xFFFF0000u;
    uint32_t bw = __float_as_uint(v.w) & 0xFFFF0000u;
    hi.x = (bx >> 16) | by;
    hi.y = (bz >> 16) | bw;
    float lx = v.x - __uint_as_float(bx);
    float ly = v.y - __uint_as_float(by);
    float lz = v.z - __uint_as_float(bz);
    float lw = v.w - __uint_as_float(bw);
    asm("cvt.rn.bf16x2.f32 %0, %1, %2;" : "=r"(lo.x) : "f"(ly), "f"(lx));
    asm("cvt.rn.bf16x2.f32 %0, %1, %2;" : "=r"(lo.y) : "f"(lw), "f"(lz));
}

__device__ __forceinline__ void ldm4(uint32_t* d, uint32_t addr) {
    asm volatile("ldmatrix.sync.aligned.m8n8.x4.shared.b16 {%0,%1,%2,%3}, [%4];"
                 : "=r"(d[0]), "=r"(d[1]), "=r"(d[2]), "=r"(d[3]) : "r"(addr));
}
__device__ __forceinline__ void mma16816(float* c, const uint32_t* a, uint32_t b0, uint32_t b1) {
    asm volatile(
        "mma.sync.aligned.m16n8k16.row.col.f32.bf16.bf16.f32 "
        "{%0,%1,%2,%3}, {%4,%5,%6,%7}, {%8,%9}, {%0,%1,%2,%3};"
        : "+f"(c[0]), "+f"(c[1]), "+f"(c[2]), "+f"(c[3])
        : "r"(a[0]), "r"(a[1]), "r"(a[2]), "r"(a[3]), "r"(b0), "r"(b1));
}

// =====================================================================
// Weight prep (one-time). prep_lstm: dst row r <- src row (r&3)*H + (r>>2),
// K concat [ih | hh].
// =====================================================================
__global__ void __launch_bounds__(256) prep_lstm(
    const float* __restrict__ ih, int Kih, const float* __restrict__ hh,
    unsigned short* __restrict__ hi, unsigned short* __restrict__ lo, int Ktot)
{
    int r = blockIdx.y;
    int k = blockIdx.x * 1024 + threadIdx.x * 4;
    if (k >= Ktot) return;
    int srow = (r & 3) * Hsz + (r >> 2);
    const float* src = (k < Kih) ? (ih + (size_t)srow * Kih + k)
                                 : (hh + (size_t)srow * (Ktot - Kih) + (k - Kih));
    float4 v = *reinterpret_cast<const float4*>(src);
    uint2 h2v, l2v;
    split4(v, h2v, l2v);
    size_t o = (size_t)r * Ktot + k;
    *reinterpret_cast<uint2*>(hi + o) = h2v;
    *reinterpret_cast<uint2*>(lo + o) = l2v;
}

__global__ void __launch_bounds__(256) prep_flat(
    const float* __restrict__ src, unsigned short* __restrict__ hi, unsigned short* __restrict__ lo)
{
    size_t e = ((size_t)blockIdx.x * 256 + threadIdx.x) * 4;
    float4 v = *reinterpret_cast<const float4*>(src + e);
    uint2 h2v, l2v;
    split4(v, h2v, l2v);
    *reinterpret_cast<uint2*>(hi + e) = h2v;
    *reinterpret_cast<uint2*>(lo + e) = l2v;
}

// =====================================================================
// HMMA split-bf16 GEMM. Grid (Ntot/128, KSPLIT, Mtiles).
// A rows 0..63 at a0 + z*mstride (multi-segment only used with z==0).
// partial[(z*KSPLIT + y)][64][Ntot].
// =====================================================================
__global__ void __launch_bounds__(256) hmma_kernel(
    const float* __restrict__ a0, int lda0, int K0,
    const float* __restrict__ a1, int lda1, int K1,
    const float* __restrict__ a2, int lda2,
    const unsigned short* __restrict__ bhi, const unsigned short* __restrict__ blo,
    int Ktot, int Ntot, int Kchunk, int mstride, float* __restrict__ part)
{
    extern __shared__ char smbuf[];   // Ahi 8K | Alo 8K | Bhi 16K | Blo 16K
    const int tid = threadIdx.x;
    const int n0 = blockIdx.x * 128;
    const int kbase = blockIdx.y * Kchunk;
    const int nT = Kchunk >> 6;
    const int lane = tid & 31, wid = tid >> 5;
    const int wr = wid & 3, wc = wid >> 2;
    const float* a0z = a0 + (size_t)blockIdx.z * mstride;

    float acc[8][4];
#pragma unroll
    for (int f = 0; f < 8; f++)
#pragma unroll
        for (int i = 0; i < 4; i++) acc[f][i] = 0.f;

    float4 ar[4];
    uint4 bhr[4], blr[4];

    auto load_tile = [&](int t) {
        int kt = kbase + (t << 6);
        const float* ap; int lda, kk;
        if (kt < K0)           { ap = a0z; lda = lda0; kk = kt; }
        else if (kt < K0 + K1) { ap = a1;  lda = lda1; kk = kt - K0; }
        else                   { ap = a2;  lda = lda2; kk = kt - K0 - K1; }
#pragma unroll
        for (int i = 0; i < 4; i++) {
            int gid = tid + (i << 8);
            int row = gid >> 4, f4 = gid & 15;
            ar[i] = *reinterpret_cast<const float4*>(ap + (size_t)row * lda + kk + f4 * 4);
        }
#pragma unroll
        for (int i = 0; i < 4; i++) {
            int gid = tid + (i << 8);
            int row = gid >> 3, u4 = gid & 7;
            size_t off = (size_t)(n0 + row) * Ktot + kt + u4 * 8;
            bhr[i] = *reinterpret_cast<const uint4*>(bhi + off);
            blr[i] = *reinterpret_cast<const uint4*>(blo + off);
        }
    };

    auto stage = [&]() {
#pragma unroll
        for (int i = 0; i < 4; i++) {
            int gid = tid + (i << 8);
            int row = gid >> 4, f4 = gid & 15;
            uint32_t o = row * 128 + ((f4 * 8) ^ ((row & 7) << 4));
            uint2 hv, lv;
            split4(ar[i], hv, lv);
            *reinterpret_cast<uint2*>(smbuf + o) = hv;
            *reinterpret_cast<uint2*>(smbuf + 8192 + o) = lv;
        }
#pragma unroll
        for (int i = 0; i < 4; i++) {
            int gid = tid + (i << 8);
            int row = gid >> 3, u4 = gid & 7;
            uint32_t o = row * 128 + ((u4 * 16) ^ ((row & 7) << 4));
            *reinterpret_cast<uint4*>(smbuf + 16384 + o) = bhr[i];
            *reinterpret_cast<uint4*>(smbuf + 32768 + o) = blr[i];
        }
    };

    const uint32_t smb = smem_u32(smbuf);
    const int lm = lane >> 3, lr = lane & 7;
    const uint32_t xorr = (uint32_t)lr << 4;
    const uint32_t aAddr = smb + (uint32_t)(wr * 16 + (lm & 1) * 8 + lr) * 128;
    const uint32_t aKsel = (uint32_t)((lm >> 1) * 16);
    const uint32_t bAddr = smb + 16384 + (uint32_t)(wc * 64 + (lm >> 1) * 8 + lr) * 128;
    const uint32_t bKsel = (uint32_t)((lm & 1) * 16);

    load_tile(0);

    for (int t = 0; t < nT; t++) {
        stage();
        __syncthreads();
        if (t + 1 < nT) load_tile(t + 1);
#pragma unroll
        for (int ks = 0; ks < 4; ks++) {
            uint32_t ka = ((uint32_t)(ks * 32) + aKsel) ^ xorr;
            uint32_t kb = ((uint32_t)(ks * 32) + bKsel) ^ xorr;
            uint32_t ah[4], al[4];
            ldm4(ah, aAddr + ka);
            ldm4(al, aAddr + 8192 + ka);
#pragma unroll
            for (int p = 0; p < 4; p++) {
                uint32_t bh[4], bl[4];
                ldm4(bh, bAddr + p * 2048 + kb);
                ldm4(bl, bAddr + 16384 + p * 2048 + kb);
                mma16816(acc[2 * p],     ah, bh[0], bh[1]);
                mma16816(acc[2 * p],     ah, bl[0], bl[1]);
                mma16816(acc[2 * p],     al, bh[0], bh[1]);
                mma16816(acc[2 * p + 1], ah, bh[2], bh[3]);
                mma16816(acc[2 * p + 1], ah, bl[2], bl[3]);
                mma16816(acc[2 * p + 1], al, bh[2], bh[3]);
            }
        }
        __syncthreads();
    }

    float* P = part + (size_t)(blockIdx.z * gridDim.y + blockIdx.y) * 64 * Ntot;
    const int g = lane >> 2, tg = lane & 3;
#pragma unroll
    for (int f = 0; f < 8; f++) {
        int n = n0 + wc * 64 + f * 8 + tg * 2;
        int b = wr * 16 + g;
        *reinterpret_cast<float2*>(P + (size_t)b * Ntot + n) = make_float2(acc[f][0], acc[f][1]);
        *reinterpret_cast<float2*>(P + (size_t)(b + 8) * Ntot + n) = make_float2(acc[f][2], acc[f][3]);
    }
}

// =====================================================================
// reduce kernels (fixed-order sums -> deterministic)
// =====================================================================
__global__ void __launch_bounds__(256) lstm_reduce(
    const float* __restrict__ part, int KS,
    const float* __restrict__ ba, const float* __restrict__ bb,
    float* __restrict__ h_out, float* __restrict__ c_io)
{
    int gid = blockIdx.x * 256 + threadIdx.x;   // (b,h): 65536
    int b = gid >> 10, h = gid & 1023;
    float4 s = make_float4(0.f, 0.f, 0.f, 0.f);
    for (int ks = 0; ks < KS; ks++) {
        float4 v = *reinterpret_cast<const float4*>(part + (size_t)ks * 64 * 4096 + (size_t)b * 4096 + h * 4);
        s.x += v.x; s.y += v.y; s.z += v.z; s.w += v.w;
    }
    float gi = s.x + ba[h] + bb[h];
    float gf = s.y + ba[Hsz + h] + bb[Hsz + h];
    float gg = s.z + ba[2 * Hsz + h] + bb[2 * Hsz + h];
    float go = s.w + ba[3 * Hsz + h] + bb[3 * Hsz + h];
    float c = c_io[gid];
    float cn = sigmoidf_(gf) * c + sigmoidf_(gi) * tanhf(gg);
    c_io[gid] = cn;
    h_out[gid] = sigmoidf_(go) * tanhf(cn);
}

__global__ void __launch_bounds__(256) tanh_reduce(
    const float* __restrict__ part, int KS, const float* __restrict__ bias,
    float* __restrict__ out0, float* __restrict__ out1)
{
    int gid = blockIdx.x * 256 + threadIdx.x;
    int n = (gid * 4) & 1023;
    float4 s = make_float4(0.f, 0.f, 0.f, 0.f);
    for (int ks = 0; ks < KS; ks++) {
        float4 v = *reinterpret_cast<const float4*>(part + (size_t)ks * 64 * 1024 + gid * 4);
        s.x += v.x; s.y += v.y; s.z += v.z; s.w += v.w;
    }
    float4 bi = *reinterpret_cast<const float4*>(bias + n);
    float4 r;
    r.x = tanhf(s.x + bi.x);
    r.y = tanhf(s.y + bi.y);
    r.z = tanhf(s.z + bi.z);
    r.w = tanhf(s.w + bi.w);
    *reinterpret_cast<float4*>(out0 + gid * 4) = r;
    *reinterpret_cast<float4*>(out1 + gid * 4) = r;
}

// =====================================================================
// Attention via precomputed eproj: e[l] = h2[b].eproj[b,l]; masked
// softmax; a_t = sum alpha*enc. One CTA per b, 512 threads.
// =====================================================================
__global__ void __launch_bounds__(512) att_kernel(
    const float* __restrict__ h2, const float* __restrict__ eproj,
    const float* __restrict__ enc, const int* __restrict__ masks,
    float* __restrict__ a_t)
{
    const int b = blockIdx.x;
    const int tid = threadIdx.x, lane = tid & 31, warp = tid >> 5;
    __shared__ __align__(16) float qs[HEsz];
    __shared__ float alpha[Lsz];

    qs[tid] = h2[b * Hsz + tid];
    qs[tid + 512] = h2[b * Hsz + tid + 512];
    __syncthreads();

    const float4* qs4 = reinterpret_cast<const float4*>(qs);
    const float* epb = eproj + (size_t)b * Lsz * HEsz;
    const float* encb = enc + (size_t)b * Lsz * HEsz;
#pragma unroll
    for (int i = 0; i < 8; i++) {
        int l = warp * 8 + i;
        const float4* er = reinterpret_cast<const float4*>(epb + (size_t)l * HEsz);
        float s = 0.f;
#pragma unroll
        for (int jj = 0; jj < 8; jj++) {
            float4 a = qs4[lane + jj * 32];
            float4 c = er[lane + jj * 32];
            s += a.x * c.x + a.y * c.y + a.z * c.z + a.w * c.w;
        }
#pragma unroll
        for (int off = 16; off; off >>= 1) s += __shfl_xor_sync(0xffffffffu, s, off);
        if (lane == 0) alpha[l] = s;
    }
    __syncthreads();

    if (tid < 32) {
        float v[4];
        float m = -INFINITY;
#pragma unroll
        for (int i = 0; i < 4; i++) {
            float raw = alpha[tid + 32 * i];
            v[i] = (masks[b * Lsz + tid + 32 * i] != 0) ? -INFINITY : raw;
            m = fmaxf(m, v[i]);
        }
#pragma unroll
        for (int off = 16; off; off >>= 1) m = fmaxf(m, __shfl_xor_sync(0xffffffffu, m, off));
        float s = 0.f;
#pragma unroll
        for (int i = 0; i < 4; i++) { v[i] = expf(v[i] - m); s += v[i]; }
#pragma unroll
        for (int off = 16; off; off >>= 1) s += __shfl_xor_sync(0xffffffffu, s, off);
        float inv = 1.f / s;
#pragma unroll
        for (int i = 0; i < 4; i++) alpha[tid + 32 * i] = v[i] * inv;
    }
    __syncthreads();

    float a0 = 0.f, a1 = 0.f;
#pragma unroll 4
    for (int l = 0; l < Lsz; l++) {
        float w = alpha[l];
        const float* er = encb + (size_t)l * HEsz;
        a0 += w * er[tid];
        a1 += w * er[tid + 512];
    }
    a_t[b * HEsz + tid] = a0;
    a_t[b * HEsz + tid + 512] = a1;
}

// =====================================================================
extern "C" void kernel_launch(void* const* d_in, const int* in_sizes, int n_in,
                              void* d_out, int out_size)
{
    const float* enc      = (const float*)d_in[0];
    const int*   masks    = (const int*)d_in[1];
    const float* h1i      = (const float*)d_in[2];
    const float* c1i      = (const float*)d_in[3];
    const float* h2i      = (const float*)d_in[4];
    const float* c2i      = (const float*)d_in[5];
    const float* captions = (const float*)d_in[6];
    const float* W_ih1    = (const float*)d_in[7];
    const float* W_hh1    = (const float*)d_in[8];
    const float* b_ih1    = (const float*)d_in[9];
    const float* b_hh1    = (const float*)d_in[10];
    const float* W_ih2    = (const float*)d_in[11];
    const float* W_hh2    = (const float*)d_in[12];
    const float* b_ih2    = (const float*)d_in[13];
    const float* b_hh2    = (const float*)d_in[14];
    const float* W_att    = (const float*)d_in[15];
    // d_in[16] = b_att unused (softmax shift-invariant)
    const float* W_comb   = (const float*)d_in[17];
    const float* b_comb   = (const float*)d_in[18];
    float* out = (float*)d_out;

    float *h1all, *h2b, *c1, *c2, *o, *at, *eproj, *part, *part1;
    unsigned short *b1h, *b1l, *b2h, *b2l, *bah, *bal, *bch, *bcl;
    cudaGetSymbolAddress((void**)&h1all, g_h1all);
    cudaGetSymbolAddress((void**)&h2b, g_h2);
    cudaGetSymbolAddress((void**)&c1, g_c1);
    cudaGetSymbolAddress((void**)&c2, g_c2);
    cudaGetSymbolAddress((void**)&o,  g_o);
    cudaGetSymbolAddress((void**)&at, g_at);
    cudaGetSymbolAddress((void**)&eproj, g_eproj);
    cudaGetSymbolAddress((void**)&part,  g_part);
    cudaGetSymbolAddress((void**)&part1, g_part1);
    cudaGetSymbolAddress((void**)&b1h, g_b1h);
    cudaGetSymbolAddress((void**)&b1l, g_b1l);
    cudaGetSymbolAddress((void**)&b2h, g_b2h);
    cudaGetSymbolAddress((void**)&b2l, g_b2l);
    cudaGetSymbolAddress((void**)&bah, g_bah);
    cudaGetSymbolAddress((void**)&bal, g_bal);
    cudaGetSymbolAddress((void**)&bch, g_bch);
    cudaGetSymbolAddress((void**)&bcl, g_bcl);

    cudaFuncSetAttribute(hmma_kernel, cudaFuncAttributeMaxDynamicSharedMemorySize, 49152);

    // lazy-init second stream + events (same footprint as the clean R9 run)
    static cudaStream_t s2 = nullptr;
    static cudaEvent_t evInit = nullptr;
    static cudaEvent_t evH1[Tsz];
    if (!s2) {
        cudaStreamCreateWithFlags(&s2, cudaStreamNonBlocking);
        cudaEventCreateWithFlags(&evInit, cudaEventDisableTiming);
        for (int t = 0; t < Tsz; t++)
            cudaEventCreateWithFlags(&evH1[t], cudaEventDisableTiming);
    }

    float* h2p[2] = { h2b, h2b + Bsz * Hsz };

    const size_t SB = (size_t)Bsz * Hsz * sizeof(float);
    cudaMemcpyAsync(h1all, h1i, SB, cudaMemcpyDeviceToDevice, 0);   // h1all[0] = h1_init
    cudaMemcpyAsync(c1, c1i, SB, cudaMemcpyDeviceToDevice, 0);
    cudaMemcpyAsync(h2p[0], h2i, SB, cudaMemcpyDeviceToDevice, 0);
    cudaMemcpyAsync(c2, c2i, SB, cudaMemcpyDeviceToDevice, 0);
    cudaMemsetAsync(o, 0, SB, 0);

    // one-time weight prep (main stream)
    prep_lstm<<<dim3(2, 4096), 256>>>(W_ih1, 512, W_hh1, b1h, b1l, 1536);
    prep_lstm<<<dim3(3, 4096), 256>>>(W_ih2, 2048, W_hh2, b2h, b2l, 3072);
    prep_flat<<<1024, 256>>>(W_att, bah, bal);
    prep_flat<<<2048, 256>>>(W_comb, bch, bcl);
    // one-time: eproj[b,l,h] = sum_f enc[b,l,f] * W_att[h,f]
    // (M = 8192 rows via 128 z-tiles of 64, KSPLIT 1; partials land directly in eproj)
    hmma_kernel<<<dim3(8, 1, 128), 256, 49152>>>(
        enc, HEsz, 1024, nullptr, 0, 0, nullptr, 0,
        bah, bal, 1024, 1024, 1024, 64 * HEsz, eproj);
    cudaEventRecord(evInit, 0);

    // ---- s2: LSTM1 chain free-runs (depends only on captions + itself) ----
    cudaStreamWaitEvent(s2, evInit, 0);
    for (int t = 0; t < Tsz; t++) {
        const float* cap = captions + (size_t)t * Bsz * Esz;
        float* h1cur = h1all + (size_t)t * Bsz * Hsz;
        float* h1nxt = h1all + (size_t)(t + 1) * Bsz * Hsz;
        hmma_kernel<<<dim3(32, 3), 256, 49152, s2>>>(
            cap, Esz, 512, h1cur, Hsz, 1024, nullptr, 0,
            b1h, b1l, 1536, 4096, 512, 0, part1);
        lstm_reduce<<<256, 256, 0, s2>>>(part1, 3, b_ih1, b_hh1, h1nxt, c1);
        cudaEventRecord(evH1[t], s2);
    }

    // ---- main chain: lstm2 -> attention -> comb (5 launches/step) ----
    int cur = 0;
    for (int t = 0; t < Tsz; t++) {
        int nxt = cur ^ 1;
        float* h1nxt = h1all + (size_t)(t + 1) * Bsz * Hsz;
        cudaStreamWaitEvent(0, evH1[t], 0);
        // LSTM2: [h1 | o | h2] ; K=3072, KSPLIT 4
        hmma_kernel<<<dim3(32, 4), 256, 49152>>>(
            h1nxt, Hsz, 1024, o, Hsz, 1024, h2p[cur], Hsz,
            b2h, b2l, 3072, 4096, 768, 0, part);
        lstm_reduce<<<256, 256>>>(part, 4, b_ih2, b_hh2, h2p[nxt], c2);
        // attention: e = h2 . eproj, masked softmax, weighted enc sum
        att_kernel<<<64, 512>>>(h2p[nxt], eproj, enc, masks, at);
        // o_t = tanh([a_t | h2] @ W_comb^T + b_comb) ; K=2048, KSPLIT 4
        hmma_kernel<<<dim3(8, 4), 256, 49152>>>(
            at, Hsz, 1024, h2p[nxt], Hsz, 1024, nullptr, 0,
            bch, bcl, 2048, 1024, 512, 0, part);
        tanh_reduce<<<64, 256>>>(part, 4, b_comb, o, out + (size_t)t * Bsz * Hsz);
        cur = nxt;
    }
}

// round 12
// speedup vs baseline: 1.2679x; 1.2679x over previous
#include <cuda_runtime.h>
#include <math.h>
#include <stdint.h>

#define Bsz 64
#define Lsz 128
#define Tsz 48
#define Esz 512
#define HEsz 1024
#define Hsz 1024

// ---------------- device-global scratch ----------------
__device__ float g_h1all[(Tsz + 1) * Bsz * Hsz];   // h1 for every step (s2-owned)
__device__ float g_h2[2][Bsz * Hsz];
__device__ float g_c1[Bsz * Hsz];
__device__ float g_c2[Bsz * Hsz];
__device__ float g_o[Bsz * Hsz];
__device__ float g_at[Bsz * HEsz];
__device__ float g_part[8 * Bsz * 4 * Hsz];        // split-K partials, main stream (8 slots)
__device__ float g_part1[3 * Bsz * 4 * Hsz];       // split-K partials, lstm1 stream (s2)

// pre-split bf16 weights (bits as ushort)
__device__ unsigned short g_b1h[4096 * 1536], g_b1l[4096 * 1536];   // [W_ih1|W_hh1] gate-interleaved
__device__ unsigned short g_b2h[4096 * 3072], g_b2l[4096 * 3072];   // [W_ih2|W_hh2] gate-interleaved
__device__ unsigned short g_bqh[1024 * 1024], g_bql[1024 * 1024];   // W_att transposed
__device__ unsigned short g_bch[1024 * 2048], g_bcl[1024 * 2048];   // W_comb direct

__device__ __forceinline__ float sigmoidf_(float x) { return 1.f / (1.f + expf(-x)); }

__device__ __forceinline__ uint32_t smem_u32(const void* p) {
    uint32_t a;
    asm("{ .reg .u64 t; cvta.to.shared.u64 t, %1; cvt.u32.u64 %0, t; }" : "=r"(a) : "l"(p));
    return a;
}

// fp32 -> bf16 hi (exact truncation) + bf16 lo (rounded residual)
__device__ __forceinline__ void split4(float4 v, uint2& hi, uint2& lo) {
    uint32_t bx = __float_as_uint(v.x) & 0xFFFF0000u;
    uint32_t by = __float_as_uint(v.y) & 0xFFFF0000u;
    uint32_t bz = __float_as_uint(v.z) & 0xFFFF0000u;
    uint32_t bw = __float_as_uint(v.w) & 0xFFFF0000u;
    hi.x = (bx >> 16) | by;
    hi.y = (bz >> 16) | bw;
    float lx = v.x - __uint_as_float(bx);
    float ly = v.y - __uint_as_float(by);
    float lz = v.z - __uint_as_float(bz);
    float lw = v.w - __uint_as_float(bw);
    asm("cvt.rn.bf16x2.f32 %0, %1, %2;" : "=r"(lo.x) : "f"(ly), "f"(lx));
    asm("cvt.rn.bf16x2.f32 %0, %1, %2;" : "=r"(lo.y) : "f"(lw), "f"(lz));
}

__device__ __forceinline__ void ldm4(uint32_t* d, uint32_t addr) {
    asm volatile("ldmatrix.sync.aligned.m8n8.x4.shared.b16 {%0,%1,%2,%3}, [%4];"
                 : "=r"(d[0]), "=r"(d[1]), "=r"(d[2]), "=r"(d[3]) : "r"(addr));
}
__device__ __forceinline__ void mma16816(float* c, const uint32_t* a, uint32_t b0, uint32_t b1) {
    asm volatile(
        "mma.sync.aligned.m16n8k16.row.col.f32.bf16.bf16.f32 "
        "{%0,%1,%2,%3}, {%4,%5,%6,%7}, {%8,%9}, {%0,%1,%2,%3};"
        : "+f"(c[0]), "+f"(c[1]), "+f"(c[2]), "+f"(c[3])
        : "r"(a[0]), "r"(a[1]), "r"(a[2]), "r"(a[3]), "r"(b0), "r"(b1));
}

// =====================================================================
// Weight prep (one-time). prep_lstm: dst row r <- src row (r&3)*H + (r>>2),
// K concat [ih | hh].
// =====================================================================
__global__ void __launch_bounds__(256) prep_lstm(
    const float* __restrict__ ih, int Kih, const float* __restrict__ hh,
    unsigned short* __restrict__ hi, unsigned short* __restrict__ lo, int Ktot)
{
    int r = blockIdx.y;
    int k = blockIdx.x * 1024 + threadIdx.x * 4;
    if (k >= Ktot) return;
    int srow = (r & 3) * Hsz + (r >> 2);
    const float* src = (k < Kih) ? (ih + (size_t)srow * Kih + k)
                                 : (hh + (size_t)srow * (Ktot - Kih) + (k - Kih));
    float4 v = *reinterpret_cast<const float4*>(src);
    uint2 h2v, l2v;
    split4(v, h2v, l2v);
    size_t o = (size_t)r * Ktot + k;
    *reinterpret_cast<uint2*>(hi + o) = h2v;
    *reinterpret_cast<uint2*>(lo + o) = l2v;
}

__global__ void __launch_bounds__(256) prep_flat(
    const float* __restrict__ src, unsigned short* __restrict__ hi, unsigned short* __restrict__ lo)
{
    size_t e = ((size_t)blockIdx.x * 256 + threadIdx.x) * 4;
    float4 v = *reinterpret_cast<const float4*>(src + e);
    uint2 h2v, l2v;
    split4(v, h2v, l2v);
    *reinterpret_cast<uint2*>(hi + e) = h2v;
    *reinterpret_cast<uint2*>(lo + e) = l2v;
}

// dst[f*H + h] = W_att[h*HE + f], split
__global__ void __launch_bounds__(256) prep_q(
    const float* __restrict__ src, unsigned short* __restrict__ hi, unsigned short* __restrict__ lo)
{
    __shared__ float t[32][33];
    int bx = blockIdx.x * 32, by = blockIdx.y * 32;
    int x = threadIdx.x & 31, y4 = (threadIdx.x >> 5) * 4;
#pragma unroll
    for (int i = 0; i < 4; i++) t[y4 + i][x] = src[(size_t)(by + y4 + i) * HEsz + bx + x];
    __syncthreads();
#pragma unroll
    for (int i = 0; i < 4; i++) {
        float v = t[x][y4 + i];
        uint32_t b = __float_as_uint(v) & 0xFFFF0000u;
        float rr = v - __uint_as_float(b);
        uint32_t lb;
        asm("cvt.rn.bf16x2.f32 %0, %1, %2;" : "=r"(lb) : "f"(0.f), "f"(rr));
        size_t o = (size_t)(bx + y4 + i) * Hsz + by + x;
        hi[o] = (unsigned short)(b >> 16);
        lo[o] = (unsigned short)(lb & 0xFFFF);
    }
}

// =====================================================================
// HMMA split-bf16 GEMM. Grid (Ntot/128, KSPLIT, Mtiles).
// =====================================================================
__global__ void __launch_bounds__(256) hmma_kernel(
    const float* __restrict__ a0, int lda0, int K0,
    const float* __restrict__ a1, int lda1, int K1,
    const float* __restrict__ a2, int lda2,
    const unsigned short* __restrict__ bhi, const unsigned short* __restrict__ blo,
    int Ktot, int Ntot, int Kchunk, int mstride, float* __restrict__ part)
{
    extern __shared__ char smbuf[];   // Ahi 8K | Alo 8K | Bhi 16K | Blo 16K
    const int tid = threadIdx.x;
    const int n0 = blockIdx.x * 128;
    const int kbase = blockIdx.y * Kchunk;
    const int nT = Kchunk >> 6;
    const int lane = tid & 31, wid = tid >> 5;
    const int wr = wid & 3, wc = wid >> 2;
    const float* a0z = a0 + (size_t)blockIdx.z * mstride;

    float acc[8][4];
#pragma unroll
    for (int f = 0; f < 8; f++)
#pragma unroll
        for (int i = 0; i < 4; i++) acc[f][i] = 0.f;

    float4 ar[4];
    uint4 bhr[4], blr[4];

    auto load_tile = [&](int t) {
        int kt = kbase + (t << 6);
        const float* ap; int lda, kk;
        if (kt < K0)           { ap = a0z; lda = lda0; kk = kt; }
        else if (kt < K0 + K1) { ap = a1;  lda = lda1; kk = kt - K0; }
        else                   { ap = a2;  lda = lda2; kk = kt - K0 - K1; }
#pragma unroll
        for (int i = 0; i < 4; i++) {
            int gid = tid + (i << 8);
            int row = gid >> 4, f4 = gid & 15;
            ar[i] = *reinterpret_cast<const float4*>(ap + (size_t)row * lda + kk + f4 * 4);
        }
#pragma unroll
        for (int i = 0; i < 4; i++) {
            int gid = tid + (i << 8);
            int row = gid >> 3, u4 = gid & 7;
            size_t off = (size_t)(n0 + row) * Ktot + kt + u4 * 8;
            bhr[i] = *reinterpret_cast<const uint4*>(bhi + off);
            blr[i] = *reinterpret_cast<const uint4*>(blo + off);
        }
    };

    auto stage = [&]() {
#pragma unroll
        for (int i = 0; i < 4; i++) {
            int gid = tid + (i << 8);
            int row = gid >> 4, f4 = gid & 15;
            uint32_t o = row * 128 + ((f4 * 8) ^ ((row & 7) << 4));
            uint2 hv, lv;
            split4(ar[i], hv, lv);
            *reinterpret_cast<uint2*>(smbuf + o) = hv;
            *reinterpret_cast<uint2*>(smbuf + 8192 + o) = lv;
        }
#pragma unroll
        for (int i = 0; i < 4; i++) {
            int gid = tid + (i << 8);
            int row = gid >> 3, u4 = gid & 7;
            uint32_t o = row * 128 + ((u4 * 16) ^ ((row & 7) << 4));
            *reinterpret_cast<uint4*>(smbuf + 16384 + o) = bhr[i];
            *reinterpret_cast<uint4*>(smbuf + 32768 + o) = blr[i];
        }
    };

    const uint32_t smb = smem_u32(smbuf);
    const int lm = lane >> 3, lr = lane & 7;
    const uint32_t xorr = (uint32_t)lr << 4;
    const uint32_t aAddr = smb + (uint32_t)(wr * 16 + (lm & 1) * 8 + lr) * 128;
    const uint32_t aKsel = (uint32_t)((lm >> 1) * 16);
    const uint32_t bAddr = smb + 16384 + (uint32_t)(wc * 64 + (lm >> 1) * 8 + lr) * 128;
    const uint32_t bKsel = (uint32_t)((lm & 1) * 16);

    load_tile(0);

    for (int t = 0; t < nT; t++) {
        stage();
        __syncthreads();
        if (t + 1 < nT) load_tile(t + 1);
#pragma unroll
        for (int ks = 0; ks < 4; ks++) {
            uint32_t ka = ((uint32_t)(ks * 32) + aKsel) ^ xorr;
            uint32_t kb = ((uint32_t)(ks * 32) + bKsel) ^ xorr;
            uint32_t ah[4], al[4];
            ldm4(ah, aAddr + ka);
            ldm4(al, aAddr + 8192 + ka);
#pragma unroll
            for (int p = 0; p < 4; p++) {
                uint32_t bh[4], bl[4];
                ldm4(bh, bAddr + p * 2048 + kb);
                ldm4(bl, bAddr + 16384 + p * 2048 + kb);
                mma16816(acc[2 * p],     ah, bh[0], bh[1]);
                mma16816(acc[2 * p],     ah, bl[0], bl[1]);
                mma16816(acc[2 * p],     al, bh[0], bh[1]);
                mma16816(acc[2 * p + 1], ah, bh[2], bh[3]);
                mma16816(acc[2 * p + 1], ah, bl[2], bl[3]);
                mma16816(acc[2 * p + 1], al, bh[2], bh[3]);
            }
        }
        __syncthreads();
    }

    float* P = part + (size_t)(blockIdx.z * gridDim.y + blockIdx.y) * 64 * Ntot;
    const int g = lane >> 2, tg = lane & 3;
#pragma unroll
    for (int f = 0; f < 8; f++) {
        int n = n0 + wc * 64 + f * 8 + tg * 2;
        int b = wr * 16 + g;
        *reinterpret_cast<float2*>(P + (size_t)b * Ntot + n) = make_float2(acc[f][0], acc[f][1]);
        *reinterpret_cast<float2*>(P + (size_t)(b + 8) * Ntot + n) = make_float2(acc[f][2], acc[f][3]);
    }
}

// =====================================================================
// reduce kernels (fixed-order sums -> deterministic)
// =====================================================================
__global__ void __launch_bounds__(256) lstm_reduce(
    const float* __restrict__ part, int KS,
    const float* __restrict__ ba, const float* __restrict__ bb,
    float* __restrict__ h_out, float* __restrict__ c_io)
{
    int gid = blockIdx.x * 256 + threadIdx.x;   // (b,h): 65536
    int b = gid >> 10, h = gid & 1023;
    float4 s = make_float4(0.f, 0.f, 0.f, 0.f);
    for (int ks = 0; ks < KS; ks++) {
        float4 v = *reinterpret_cast<const float4*>(part + (size_t)ks * 64 * 4096 + (size_t)b * 4096 + h * 4);
        s.x += v.x; s.y += v.y; s.z += v.z; s.w += v.w;
    }
    float gi = s.x + ba[h] + bb[h];
    float gf = s.y + ba[Hsz + h] + bb[Hsz + h];
    float gg = s.z + ba[2 * Hsz + h] + bb[2 * Hsz + h];
    float go = s.w + ba[3 * Hsz + h] + bb[3 * Hsz + h];
    float c = c_io[gid];
    float cn = sigmoidf_(gf) * c + sigmoidf_(gi) * tanhf(gg);
    c_io[gid] = cn;
    h_out[gid] = sigmoidf_(go) * tanhf(cn);
}

__global__ void __launch_bounds__(256) tanh_reduce(
    const float* __restrict__ part, int KS, const float* __restrict__ bias,
    float* __restrict__ out0, float* __restrict__ out1)
{
    int gid = blockIdx.x * 256 + threadIdx.x;
    int n = (gid * 4) & 1023;
    float4 s = make_float4(0.f, 0.f, 0.f, 0.f);
    for (int ks = 0; ks < KS; ks++) {
        float4 v = *reinterpret_cast<const float4*>(part + (size_t)ks * 64 * 1024 + gid * 4);
        s.x += v.x; s.y += v.y; s.z += v.z; s.w += v.w;
    }
    float4 bi = *reinterpret_cast<const float4*>(bias + n);
    float4 r;
    r.x = tanhf(s.x + bi.x);
    r.y = tanhf(s.y + bi.y);
    r.z = tanhf(s.z + bi.z);
    r.w = tanhf(s.w + bi.w);
    *reinterpret_cast<float4*>(out0 + gid * 4) = r;
    *reinterpret_cast<float4*>(out1 + gid * 4) = r;
}

// =====================================================================
// Merged attention: sums q split-K partials (KSQ slots), e = q.enc,
// masked softmax, weighted sum -> a_t. One CTA per b, 512 threads.
// =====================================================================
__global__ void __launch_bounds__(512) att_kernel(
    const float* __restrict__ qpart, int KSQ, const float* __restrict__ enc,
    const int* __restrict__ masks, float* __restrict__ a_t)
{
    const int b = blockIdx.x;
    const int tid = threadIdx.x, lane = tid & 31, warp = tid >> 5;
    __shared__ __align__(16) float qs[HEsz];
    __shared__ float alpha[Lsz];

#pragma unroll
    for (int i = 0; i < 2; i++) {
        int f = tid + 512 * i;
        float s = 0.f;
        for (int ks = 0; ks < KSQ; ks++)
            s += qpart[(size_t)ks * 64 * HEsz + b * HEsz + f];
        qs[f] = s;
    }
    __syncthreads();

    const float4* qs4 = reinterpret_cast<const float4*>(qs);
    const float* encb = enc + (size_t)b * Lsz * HEsz;
#pragma unroll
    for (int i = 0; i < 8; i++) {
        int l = warp * 8 + i;
        const float4* er = reinterpret_cast<const float4*>(encb + (size_t)l * HEsz);
        float s = 0.f;
#pragma unroll
        for (int jj = 0; jj < 8; jj++) {
            float4 a = qs4[lane + jj * 32];
            float4 c = er[lane + jj * 32];
            s += a.x * c.x + a.y * c.y + a.z * c.z + a.w * c.w;
        }
#pragma unroll
        for (int off = 16; off; off >>= 1) s += __shfl_xor_sync(0xffffffffu, s, off);
        if (lane == 0) alpha[l] = s;
    }
    __syncthreads();

    if (tid < 32) {
        float v[4];
        float m = -INFINITY;
#pragma unroll
        for (int i = 0; i < 4; i++) {
            float raw = alpha[tid + 32 * i];
            v[i] = (masks[b * Lsz + tid + 32 * i] != 0) ? -INFINITY : raw;
            m = fmaxf(m, v[i]);
        }
#pragma unroll
        for (int off = 16; off; off >>= 1) m = fmaxf(m, __shfl_xor_sync(0xffffffffu, m, off));
        float s = 0.f;
#pragma unroll
        for (int i = 0; i < 4; i++) { v[i] = expf(v[i] - m); s += v[i]; }
#pragma unroll
        for (int off = 16; off; off >>= 1) s += __shfl_xor_sync(0xffffffffu, s, off);
        float inv = 1.f / s;
#pragma unroll
        for (int i = 0; i < 4; i++) alpha[tid + 32 * i] = v[i] * inv;
    }
    __syncthreads();

    float a0 = 0.f, a1 = 0.f;
#pragma unroll 4
    for (int l = 0; l < Lsz; l++) {
        float w = alpha[l];
        const float* er = encb + (size_t)l * HEsz;
        a0 += w * er[tid];
        a1 += w * er[tid + 512];
    }
    a_t[b * HEsz + tid] = a0;
    a_t[b * HEsz + tid + 512] = a1;
}

// =====================================================================
extern "C" void kernel_launch(void* const* d_in, const int* in_sizes, int n_in,
                              void* d_out, int out_size)
{
    const float* enc      = (const float*)d_in[0];
    const int*   masks    = (const int*)d_in[1];
    const float* h1i      = (const float*)d_in[2];
    const float* c1i      = (const float*)d_in[3];
    const float* h2i      = (const float*)d_in[4];
    const float* c2i      = (const float*)d_in[5];
    const float* captions = (const float*)d_in[6];
    const float* W_ih1    = (const float*)d_in[7];
    const float* W_hh1    = (const float*)d_in[8];
    const float* b_ih1    = (const float*)d_in[9];
    const float* b_hh1    = (const float*)d_in[10];
    const float* W_ih2    = (const float*)d_in[11];
    const float* W_hh2    = (const float*)d_in[12];
    const float* b_ih2    = (const float*)d_in[13];
    const float* b_hh2    = (const float*)d_in[14];
    const float* W_att    = (const float*)d_in[15];
    // d_in[16] = b_att unused (softmax shift-invariant)
    const float* W_comb   = (const float*)d_in[17];
    const float* b_comb   = (const float*)d_in[18];
    float* out = (float*)d_out;

    float *h1all, *h2b, *c1, *c2, *o, *at, *part, *part1;
    unsigned short *b1h, *b1l, *b2h, *b2l, *bqh, *bql, *bch, *bcl;
    cudaGetSymbolAddress((void**)&h1all, g_h1all);
    cudaGetSymbolAddress((void**)&h2b, g_h2);
    cudaGetSymbolAddress((void**)&c1, g_c1);
    cudaGetSymbolAddress((void**)&c2, g_c2);
    cudaGetSymbolAddress((void**)&o,  g_o);
    cudaGetSymbolAddress((void**)&at, g_at);
    cudaGetSymbolAddress((void**)&part,  g_part);
    cudaGetSymbolAddress((void**)&part1, g_part1);
    cudaGetSymbolAddress((void**)&b1h, g_b1h);
    cudaGetSymbolAddress((void**)&b1l, g_b1l);
    cudaGetSymbolAddress((void**)&b2h, g_b2h);
    cudaGetSymbolAddress((void**)&b2l, g_b2l);
    cudaGetSymbolAddress((void**)&bqh, g_bqh);
    cudaGetSymbolAddress((void**)&bql, g_bql);
    cudaGetSymbolAddress((void**)&bch, g_bch);
    cudaGetSymbolAddress((void**)&bcl, g_bcl);

    cudaFuncSetAttribute(hmma_kernel, cudaFuncAttributeMaxDynamicSharedMemorySize, 49152);

    // lazy-init second stream + events (same footprint as the clean R9 run)
    static cudaStream_t s2 = nullptr;
    static cudaEvent_t evInit = nullptr;
    static cudaEvent_t evH1[Tsz];
    if (!s2) {
        cudaStreamCreateWithFlags(&s2, cudaStreamNonBlocking);
        cudaEventCreateWithFlags(&evInit, cudaEventDisableTiming);
        for (int t = 0; t < Tsz; t++)
            cudaEventCreateWithFlags(&evH1[t], cudaEventDisableTiming);
    }

    float* h2p[2] = { h2b, h2b + Bsz * Hsz };

    const size_t SB = (size_t)Bsz * Hsz * sizeof(float);
    cudaMemcpyAsync(h1all, h1i, SB, cudaMemcpyDeviceToDevice, 0);   // h1all[0] = h1_init
    cudaMemcpyAsync(c1, c1i, SB, cudaMemcpyDeviceToDevice, 0);
    cudaMemcpyAsync(h2p[0], h2i, SB, cudaMemcpyDeviceToDevice, 0);
    cudaMemcpyAsync(c2, c2i, SB, cudaMemcpyDeviceToDevice, 0);
    cudaMemsetAsync(o, 0, SB, 0);

    // one-time weight prep (main stream)
    prep_lstm<<<dim3(2, 4096), 256>>>(W_ih1, 512, W_hh1, b1h, b1l, 1536);
    prep_lstm<<<dim3(3, 4096), 256>>>(W_ih2, 2048, W_hh2, b2h, b2l, 3072);
    prep_q<<<dim3(32, 32), 256>>>(W_att, bqh, bql);
    prep_flat<<<2048, 256>>>(W_comb, bch, bcl);
    cudaEventRecord(evInit, 0);

    // ---- s2: LSTM1 chain free-runs (depends only on captions + itself) ----
    cudaStreamWaitEvent(s2, evInit, 0);
    for (int t = 0; t < Tsz; t++) {
        const float* cap = captions + (size_t)t * Bsz * Esz;
        float* h1cur = h1all + (size_t)t * Bsz * Hsz;
        float* h1nxt = h1all + (size_t)(t + 1) * Bsz * Hsz;
        hmma_kernel<<<dim3(32, 3), 256, 49152, s2>>>(
            cap, Esz, 512, h1cur, Hsz, 1024, nullptr, 0,
            b1h, b1l, 1536, 4096, 512, 0, part1);
        lstm_reduce<<<256, 256, 0, s2>>>(part1, 3, b_ih1, b_hh1, h1nxt, c1);
        cudaEventRecord(evH1[t], s2);
    }

    // ---- main chain: lstm2 -> q -> attention -> comb (6 launches/step) ----
    int cur = 0;
    for (int t = 0; t < Tsz; t++) {
        int nxt = cur ^ 1;
        float* h1nxt = h1all + (size_t)(t + 1) * Bsz * Hsz;
        cudaStreamWaitEvent(0, evH1[t], 0);
        // LSTM2: [h1 | o | h2] ; K=3072, KSPLIT 8 (6 tiles/CTA, 256 CTAs)
        hmma_kernel<<<dim3(32, 8), 256, 49152>>>(
            h1nxt, Hsz, 1024, o, Hsz, 1024, h2p[cur], Hsz,
            b2h, b2l, 3072, 4096, 384, 0, part);
        lstm_reduce<<<256, 256>>>(part, 8, b_ih2, b_hh2, h2p[nxt], c2);
        // q = h2 @ W_att ; K=1024, KSPLIT 8 (2 tiles/CTA)
        hmma_kernel<<<dim3(8, 8), 256, 49152>>>(
            h2p[nxt], Hsz, 1024, nullptr, 0, 0, nullptr, 0,
            bqh, bql, 1024, 1024, 128, 0, part);
        // merged attention (sums 8 q partials inline)
        att_kernel<<<64, 512>>>(part, 8, enc, masks, at);
        // o_t = tanh([a_t | h2] @ W_comb^T + b_comb) ; K=2048, KSPLIT 8 (4 tiles/CTA)
        hmma_kernel<<<dim3(8, 8), 256, 49152>>>(
            at, Hsz, 1024, h2p[nxt], Hsz, 1024, nullptr, 0,
            bch, bcl, 2048, 1024, 256, 0, part);
        tanh_reduce<<<64, 256>>>(part, 8, b_comb, o, out + (size_t)t * Bsz * Hsz);
        cur = nxt;
    }
}

// round 13
// speedup vs baseline: 1.2744x; 1.0051x over previous
#include <cuda_runtime.h>
#include <math.h>
#include <stdint.h>

#define Bsz 64
#define Lsz 128
#define Tsz 48
#define Esz 512
#define HEsz 1024
#define Hsz 1024

// ---------------- device-global scratch ----------------
__device__ float g_h1all[(Tsz + 1) * Bsz * Hsz];   // h1 for every step (s2-owned)
__device__ float g_h2[2][Bsz * Hsz];
__device__ float g_c1[Bsz * Hsz];
__device__ float g_c2[Bsz * Hsz];
__device__ float g_o[Bsz * Hsz];
__device__ float g_at[Bsz * HEsz];
__device__ float g_e[Bsz * Lsz];
__device__ float g_part[8 * Bsz * 4 * Hsz];        // split-K partials, main (8 big or 16 small slots)
__device__ float g_part1[3 * Bsz * 4 * Hsz];       // split-K partials, lstm1 stream (s2)

// pre-split bf16 weights (bits as ushort)
__device__ unsigned short g_b1h[4096 * 1536], g_b1l[4096 * 1536];   // [W_ih1|W_hh1] gate-interleaved
__device__ unsigned short g_b2h[4096 * 3072], g_b2l[4096 * 3072];   // [W_ih2|W_hh2] gate-interleaved
__device__ unsigned short g_bqh[1024 * 1024], g_bql[1024 * 1024];   // W_att transposed
__device__ unsigned short g_bch[1024 * 2048], g_bcl[1024 * 2048];   // W_comb direct

__device__ __forceinline__ float sigmoidf_(float x) { return 1.f / (1.f + expf(-x)); }

__device__ __forceinline__ uint32_t smem_u32(const void* p) {
    uint32_t a;
    asm("{ .reg .u64 t; cvta.to.shared.u64 t, %1; cvt.u32.u64 %0, t; }" : "=r"(a) : "l"(p));
    return a;
}

// fp32 -> bf16 hi (exact truncation) + bf16 lo (rounded residual)
__device__ __forceinline__ void split4(float4 v, uint2& hi, uint2& lo) {
    uint32_t bx = __float_as_uint(v.x) & 0xFFFF0000u;
    uint32_t by = __float_as_uint(v.y) & 0xFFFF0000u;
    uint32_t bz = __float_as_uint(v.z) & 0xFFFF0000u;
    uint32_t bw = __float_as_uint(v.w) & 0xFFFF0000u;
    hi.x = (bx >> 16) | by;
    hi.y = (bz >> 16) | bw;
    float lx = v.x - __uint_as_float(bx);
    float ly = v.y - __uint_as_float(by);
    float lz = v.z - __uint_as_float(bz);
    float lw = v.w - __uint_as_float(bw);
    asm("cvt.rn.bf16x2.f32 %0, %1, %2;" : "=r"(lo.x) : "f"(ly), "f"(lx));
    asm("cvt.rn.bf16x2.f32 %0, %1, %2;" : "=r"(lo.y) : "f"(lw), "f"(lz));
}

__device__ __forceinline__ void ldm4(uint32_t* d, uint32_t addr) {
    asm volatile("ldmatrix.sync.aligned.m8n8.x4.shared.b16 {%0,%1,%2,%3}, [%4];"
                 : "=r"(d[0]), "=r"(d[1]), "=r"(d[2]), "=r"(d[3]) : "r"(addr));
}
__device__ __forceinline__ void mma16816(float* c, const uint32_t* a, uint32_t b0, uint32_t b1) {
    asm volatile(
        "mma.sync.aligned.m16n8k16.row.col.f32.bf16.bf16.f32 "
        "{%0,%1,%2,%3}, {%4,%5,%6,%7}, {%8,%9}, {%0,%1,%2,%3};"
        : "+f"(c[0]), "+f"(c[1]), "+f"(c[2]), "+f"(c[3])
        : "r"(a[0]), "r"(a[1]), "r"(a[2]), "r"(a[3]), "r"(b0), "r"(b1));
}

// =====================================================================
// Weight prep (one-time). prep_lstm: dst row r <- src row (r&3)*H + (r>>2),
// K concat [ih | hh].
// =====================================================================
__global__ void __launch_bounds__(256) prep_lstm(
    const float* __restrict__ ih, int Kih, const float* __restrict__ hh,
    unsigned short* __restrict__ hi, unsigned short* __restrict__ lo, int Ktot)
{
    int r = blockIdx.y;
    int k = blockIdx.x * 1024 + threadIdx.x * 4;
    if (k >= Ktot) return;
    int srow = (r & 3) * Hsz + (r >> 2);
    const float* src = (k < Kih) ? (ih + (size_t)srow * Kih + k)
                                 : (hh + (size_t)srow * (Ktot - Kih) + (k - Kih));
    float4 v = *reinterpret_cast<const float4*>(src);
    uint2 h2v, l2v;
    split4(v, h2v, l2v);
    size_t o = (size_t)r * Ktot + k;
    *reinterpret_cast<uint2*>(hi + o) = h2v;
    *reinterpret_cast<uint2*>(lo + o) = l2v;
}

__global__ void __launch_bounds__(256) prep_flat(
    const float* __restrict__ src, unsigned short* __restrict__ hi, unsigned short* __restrict__ lo)
{
    size_t e = ((size_t)blockIdx.x * 256 + threadIdx.x) * 4;
    float4 v = *reinterpret_cast<const float4*>(src + e);
    uint2 h2v, l2v;
    split4(v, h2v, l2v);
    *reinterpret_cast<uint2*>(hi + e) = h2v;
    *reinterpret_cast<uint2*>(lo + e) = l2v;
}

// dst[f*H + h] = W_att[h*HE + f], split
__global__ void __launch_bounds__(256) prep_q(
    const float* __restrict__ src, unsigned short* __restrict__ hi, unsigned short* __restrict__ lo)
{
    __shared__ float t[32][33];
    int bx = blockIdx.x * 32, by = blockIdx.y * 32;
    int x = threadIdx.x & 31, y4 = (threadIdx.x >> 5) * 4;
#pragma unroll
    for (int i = 0; i < 4; i++) t[y4 + i][x] = src[(size_t)(by + y4 + i) * HEsz + bx + x];
    __syncthreads();
#pragma unroll
    for (int i = 0; i < 4; i++) {
        float v = t[x][y4 + i];
        uint32_t b = __float_as_uint(v) & 0xFFFF0000u;
        float rr = v - __uint_as_float(b);
        uint32_t lb;
        asm("cvt.rn.bf16x2.f32 %0, %1, %2;" : "=r"(lb) : "f"(0.f), "f"(rr));
        size_t o = (size_t)(bx + y4 + i) * Hsz + by + x;
        hi[o] = (unsigned short)(b >> 16);
        lo[o] = (unsigned short)(lb & 0xFFFF);
    }
}

// =====================================================================
// HMMA split-bf16 GEMM. Grid (Ntot/128, KSPLIT, Mtiles).
// =====================================================================
__global__ void __launch_bounds__(256) hmma_kernel(
    const float* __restrict__ a0, int lda0, int K0,
    const float* __restrict__ a1, int lda1, int K1,
    const float* __restrict__ a2, int lda2,
    const unsigned short* __restrict__ bhi, const unsigned short* __restrict__ blo,
    int Ktot, int Ntot, int Kchunk, int mstride, float* __restrict__ part)
{
    extern __shared__ char smbuf[];   // Ahi 8K | Alo 8K | Bhi 16K | Blo 16K
    const int tid = threadIdx.x;
    const int n0 = blockIdx.x * 128;
    const int kbase = blockIdx.y * Kchunk;
    const int nT = Kchunk >> 6;
    const int lane = tid & 31, wid = tid >> 5;
    const int wr = wid & 3, wc = wid >> 2;
    const float* a0z = a0 + (size_t)blockIdx.z * mstride;

    float acc[8][4];
#pragma unroll
    for (int f = 0; f < 8; f++)
#pragma unroll
        for (int i = 0; i < 4; i++) acc[f][i] = 0.f;

    float4 ar[4];
    uint4 bhr[4], blr[4];

    auto load_tile = [&](int t) {
        int kt = kbase + (t << 6);
        const float* ap; int lda, kk;
        if (kt < K0)           { ap = a0z; lda = lda0; kk = kt; }
        else if (kt < K0 + K1) { ap = a1;  lda = lda1; kk = kt - K0; }
        else                   { ap = a2;  lda = lda2; kk = kt - K0 - K1; }
#pragma unroll
        for (int i = 0; i < 4; i++) {
            int gid = tid + (i << 8);
            int row = gid >> 4, f4 = gid & 15;
            ar[i] = *reinterpret_cast<const float4*>(ap + (size_t)row * lda + kk + f4 * 4);
        }
#pragma unroll
        for (int i = 0; i < 4; i++) {
            int gid = tid + (i << 8);
            int row = gid >> 3, u4 = gid & 7;
            size_t off = (size_t)(n0 + row) * Ktot + kt + u4 * 8;
            bhr[i] = *reinterpret_cast<const uint4*>(bhi + off);
            blr[i] = *reinterpret_cast<const uint4*>(blo + off);
        }
    };

    auto stage = [&]() {
#pragma unroll
        for (int i = 0; i < 4; i++) {
            int gid = tid + (i << 8);
            int row = gid >> 4, f4 = gid & 15;
            uint32_t o = row * 128 + ((f4 * 8) ^ ((row & 7) << 4));
            uint2 hv, lv;
            split4(ar[i], hv, lv);
            *reinterpret_cast<uint2*>(smbuf + o) = hv;
            *reinterpret_cast<uint2*>(smbuf + 8192 + o) = lv;
        }
#pragma unroll
        for (int i = 0; i < 4; i++) {
            int gid = tid + (i << 8);
            int row = gid >> 3, u4 = gid & 7;
            uint32_t o = row * 128 + ((u4 * 16) ^ ((row & 7) << 4));
            *reinterpret_cast<uint4*>(smbuf + 16384 + o) = bhr[i];
            *reinterpret_cast<uint4*>(smbuf + 32768 + o) = blr[i];
        }
    };

    const uint32_t smb = smem_u32(smbuf);
    const int lm = lane >> 3, lr = lane & 7;
    const uint32_t xorr = (uint32_t)lr << 4;
    const uint32_t aAddr = smb + (uint32_t)(wr * 16 + (lm & 1) * 8 + lr) * 128;
    const uint32_t aKsel = (uint32_t)((lm >> 1) * 16);
    const uint32_t bAddr = smb + 16384 + (uint32_t)(wc * 64 + (lm >> 1) * 8 + lr) * 128;
    const uint32_t bKsel = (uint32_t)((lm & 1) * 16);

    load_tile(0);

    for (int t = 0; t < nT; t++) {
        stage();
        __syncthreads();
        if (t + 1 < nT) load_tile(t + 1);
#pragma unroll
        for (int ks = 0; ks < 4; ks++) {
            uint32_t ka = ((uint32_t)(ks * 32) + aKsel) ^ xorr;
            uint32_t kb = ((uint32_t)(ks * 32) + bKsel) ^ xorr;
            uint32_t ah[4], al[4];
            ldm4(ah, aAddr + ka);
            ldm4(al, aAddr + 8192 + ka);
#pragma unroll
            for (int p = 0; p < 4; p++) {
                uint32_t bh[4], bl[4];
                ldm4(bh, bAddr + p * 2048 + kb);
                ldm4(bl, bAddr + 16384 + p * 2048 + kb);
                mma16816(acc[2 * p],     ah, bh[0], bh[1]);
                mma16816(acc[2 * p],     ah, bl[0], bl[1]);
                mma16816(acc[2 * p],     al, bh[0], bh[1]);
                mma16816(acc[2 * p + 1], ah, bh[2], bh[3]);
                mma16816(acc[2 * p + 1], ah, bl[2], bl[3]);
                mma16816(acc[2 * p + 1], al, bh[2], bh[3]);
            }
        }
        __syncthreads();
    }

    float* P = part + (size_t)(blockIdx.z * gridDim.y + blockIdx.y) * 64 * Ntot;
    const int g = lane >> 2, tg = lane & 3;
#pragma unroll
    for (int f = 0; f < 8; f++) {
        int n = n0 + wc * 64 + f * 8 + tg * 2;
        int b = wr * 16 + g;
        *reinterpret_cast<float2*>(P + (size_t)b * Ntot + n) = make_float2(acc[f][0], acc[f][1]);
        *reinterpret_cast<float2*>(P + (size_t)(b + 8) * Ntot + n) = make_float2(acc[f][2], acc[f][3]);
    }
}

// =====================================================================
// reduce kernels (fixed-order sums -> deterministic)
// =====================================================================
__global__ void __launch_bounds__(256) lstm_reduce(
    const float* __restrict__ part, int KS,
    const float* __restrict__ ba, const float* __restrict__ bb,
    float* __restrict__ h_out, float* __restrict__ c_io)
{
    int gid = blockIdx.x * 256 + threadIdx.x;   // (b,h): 65536
    int b = gid >> 10, h = gid & 1023;
    float4 s = make_float4(0.f, 0.f, 0.f, 0.f);
    for (int ks = 0; ks < KS; ks++) {
        float4 v = *reinterpret_cast<const float4*>(part + (size_t)ks * 64 * 4096 + (size_t)b * 4096 + h * 4);
        s.x += v.x; s.y += v.y; s.z += v.z; s.w += v.w;
    }
    float gi = s.x + ba[h] + bb[h];
    float gf = s.y + ba[Hsz + h] + bb[Hsz + h];
    float gg = s.z + ba[2 * Hsz + h] + bb[2 * Hsz + h];
    float go = s.w + ba[3 * Hsz + h] + bb[3 * Hsz + h];
    float c = c_io[gid];
    float cn = sigmoidf_(gf) * c + sigmoidf_(gi) * tanhf(gg);
    c_io[gid] = cn;
    h_out[gid] = sigmoidf_(go) * tanhf(cn);
}

__global__ void __launch_bounds__(256) tanh_reduce(
    const float* __restrict__ part, int KS, const float* __restrict__ bias,
    float* __restrict__ out0, float* __restrict__ out1)
{
    int gid = blockIdx.x * 256 + threadIdx.x;
    int n = (gid * 4) & 1023;
    float4 s = make_float4(0.f, 0.f, 0.f, 0.f);
    for (int ks = 0; ks < KS; ks++) {
        float4 v = *reinterpret_cast<const float4*>(part + (size_t)ks * 64 * 1024 + gid * 4);
        s.x += v.x; s.y += v.y; s.z += v.z; s.w += v.w;
    }
    float4 bi = *reinterpret_cast<const float4*>(bias + n);
    float4 r;
    r.x = tanhf(s.x + bi.x);
    r.y = tanhf(s.y + bi.y);
    r.z = tanhf(s.z + bi.z);
    r.w = tanhf(s.w + bi.w);
    *reinterpret_cast<float4*>(out0 + gid * 4) = r;
    *reinterpret_cast<float4*>(out1 + gid * 4) = r;
}

// =====================================================================
// att_e: e[b,l] = q[b].enc[b,l], with q summed inline from KSQ partial
// slots. Grid (4 l-chunks, 64 b), 256 threads.
// =====================================================================
__global__ void __launch_bounds__(256) att_e_kernel(
    const float* __restrict__ qpart, int KSQ,
    const float* __restrict__ enc, float* __restrict__ e)
{
    const int b = blockIdx.y, lc = blockIdx.x;
    const int tid = threadIdx.x, lane = tid & 31, warp = tid >> 5;
    __shared__ __align__(16) float qs[HEsz];

#pragma unroll
    for (int i = 0; i < 4; i++) {
        int f = tid + 256 * i;
        float s = 0.f;
        for (int ks = 0; ks < KSQ; ks++)
            s += qpart[(size_t)ks * 64 * HEsz + b * HEsz + f];
        qs[f] = s;
    }
    __syncthreads();

    const float4* qs4 = reinterpret_cast<const float4*>(qs);
#pragma unroll
    for (int i = 0; i < 4; i++) {
        int l = lc * 32 + warp * 4 + i;
        const float4* er = reinterpret_cast<const float4*>(enc + (size_t)b * Lsz * HEsz + (size_t)l * HEsz);
        float s = 0.f;
#pragma unroll
        for (int jj = 0; jj < 8; jj++) {
            float4 a = qs4[lane + jj * 32];
            float4 c = er[lane + jj * 32];
            s += a.x * c.x + a.y * c.y + a.z * c.z + a.w * c.w;
        }
#pragma unroll
        for (int off = 16; off; off >>= 1) s += __shfl_xor_sync(0xffffffffu, s, off);
        if (lane == 0) e[b * Lsz + l] = s;
    }
}

// =====================================================================
// att_av: masked softmax (recomputed locally) + weighted enc sum for a
// 256-f chunk. Grid (4 f-chunks, 64 b), 256 threads.
// =====================================================================
__global__ void __launch_bounds__(256) att_av_kernel(
    const float* __restrict__ e, const int* __restrict__ masks,
    const float* __restrict__ enc, float* __restrict__ a_t)
{
    const int b = blockIdx.y, fc = blockIdx.x;
    const int tid = threadIdx.x;
    __shared__ float ev[Lsz];
    __shared__ float alpha[Lsz];
    if (tid < Lsz) {
        float v = e[b * Lsz + tid];
        ev[tid] = (masks[b * Lsz + tid] != 0) ? -INFINITY : v;
    }
    __syncthreads();
    if (tid < 32) {
        float v[4];
        float m = -INFINITY;
#pragma unroll
        for (int i = 0; i < 4; i++) { v[i] = ev[tid + 32 * i]; m = fmaxf(m, v[i]); }
#pragma unroll
        for (int off = 16; off; off >>= 1) m = fmaxf(m, __shfl_xor_sync(0xffffffffu, m, off));
        float s = 0.f;
#pragma unroll
        for (int i = 0; i < 4; i++) { v[i] = expf(v[i] - m); s += v[i]; }
#pragma unroll
        for (int off = 16; off; off >>= 1) s += __shfl_xor_sync(0xffffffffu, s, off);
        float inv = 1.f / s;
#pragma unroll
        for (int i = 0; i < 4; i++) alpha[tid + 32 * i] = v[i] * inv;
    }
    __syncthreads();
    const int f = fc * 256 + tid;
    const float* eb = enc + (size_t)b * Lsz * HEsz + f;
    float acc = 0.f;
#pragma unroll 4
    for (int l = 0; l < Lsz; l++) acc += alpha[l] * eb[(size_t)l * HEsz];
    a_t[b * HEsz + f] = acc;
}

// =====================================================================
extern "C" void kernel_launch(void* const* d_in, const int* in_sizes, int n_in,
                              void* d_out, int out_size)
{
    const float* enc      = (const float*)d_in[0];
    const int*   masks    = (const int*)d_in[1];
    const float* h1i      = (const float*)d_in[2];
    const float* c1i      = (const float*)d_in[3];
    const float* h2i      = (const float*)d_in[4];
    const float* c2i      = (const float*)d_in[5];
    const float* captions = (const float*)d_in[6];
    const float* W_ih1    = (const float*)d_in[7];
    const float* W_hh1    = (const float*)d_in[8];
    const float* b_ih1    = (const float*)d_in[9];
    const float* b_hh1    = (const float*)d_in[10];
    const float* W_ih2    = (const float*)d_in[11];
    const float* W_hh2    = (const float*)d_in[12];
    const float* b_ih2    = (const float*)d_in[13];
    const float* b_hh2    = (const float*)d_in[14];
    const float* W_att    = (const float*)d_in[15];
    // d_in[16] = b_att unused (softmax shift-invariant)
    const float* W_comb   = (const float*)d_in[17];
    const float* b_comb   = (const float*)d_in[18];
    float* out = (float*)d_out;

    float *h1all, *h2b, *c1, *c2, *o, *at, *e, *part, *part1;
    unsigned short *b1h, *b1l, *b2h, *b2l, *bqh, *bql, *bch, *bcl;
    cudaGetSymbolAddress((void**)&h1all, g_h1all);
    cudaGetSymbolAddress((void**)&h2b, g_h2);
    cudaGetSymbolAddress((void**)&c1, g_c1);
    cudaGetSymbolAddress((void**)&c2, g_c2);
    cudaGetSymbolAddress((void**)&o,  g_o);
    cudaGetSymbolAddress((void**)&at, g_at);
    cudaGetSymbolAddress((void**)&e,  g_e);
    cudaGetSymbolAddress((void**)&part,  g_part);
    cudaGetSymbolAddress((void**)&part1, g_part1);
    cudaGetSymbolAddress((void**)&b1h, g_b1h);
    cudaGetSymbolAddress((void**)&b1l, g_b1l);
    cudaGetSymbolAddress((void**)&b2h, g_b2h);
    cudaGetSymbolAddress((void**)&b2l, g_b2l);
    cudaGetSymbolAddress((void**)&bqh, g_bqh);
    cudaGetSymbolAddress((void**)&bql, g_bql);
    cudaGetSymbolAddress((void**)&bch, g_bch);
    cudaGetSymbolAddress((void**)&bcl, g_bcl);

    cudaFuncSetAttribute(hmma_kernel, cudaFuncAttributeMaxDynamicSharedMemorySize, 49152);

    // lazy-init second stream + events (same footprint as the clean R9/R12 runs)
    static cudaStream_t s2 = nullptr;
    static cudaEvent_t evInit = nullptr;
    static cudaEvent_t evH1[Tsz];
    if (!s2) {
        cudaStreamCreateWithFlags(&s2, cudaStreamNonBlocking);
        cudaEventCreateWithFlags(&evInit, cudaEventDisableTiming);
        for (int t = 0; t < Tsz; t++)
            cudaEventCreateWithFlags(&evH1[t], cudaEventDisableTiming);
    }

    float* h2p[2] = { h2b, h2b + Bsz * Hsz };

    const size_t SB = (size_t)Bsz * Hsz * sizeof(float);
    cudaMemcpyAsync(h1all, h1i, SB, cudaMemcpyDeviceToDevice, 0);   // h1all[0] = h1_init
    cudaMemcpyAsync(c1, c1i, SB, cudaMemcpyDeviceToDevice, 0);
    cudaMemcpyAsync(h2p[0], h2i, SB, cudaMemcpyDeviceToDevice, 0);
    cudaMemcpyAsync(c2, c2i, SB, cudaMemcpyDeviceToDevice, 0);
    cudaMemsetAsync(o, 0, SB, 0);

    // one-time weight prep (main stream)
    prep_lstm<<<dim3(2, 4096), 256>>>(W_ih1, 512, W_hh1, b1h, b1l, 1536);
    prep_lstm<<<dim3(3, 4096), 256>>>(W_ih2, 2048, W_hh2, b2h, b2l, 3072);
    prep_q<<<dim3(32, 32), 256>>>(W_att, bqh, bql);
    prep_flat<<<2048, 256>>>(W_comb, bch, bcl);
    cudaEventRecord(evInit, 0);

    // ---- s2: LSTM1 chain free-runs (depends only on captions + itself) ----
    cudaStreamWaitEvent(s2, evInit, 0);
    for (int t = 0; t < Tsz; t++) {
        const float* cap = captions + (size_t)t * Bsz * Esz;
        float* h1cur = h1all + (size_t)t * Bsz * Hsz;
        float* h1nxt = h1all + (size_t)(t + 1) * Bsz * Hsz;
        hmma_kernel<<<dim3(32, 3), 256, 49152, s2>>>(
            cap, Esz, 512, h1cur, Hsz, 1024, nullptr, 0,
            b1h, b1l, 1536, 4096, 512, 0, part1);
        lstm_reduce<<<256, 256, 0, s2>>>(part1, 3, b_ih1, b_hh1, h1nxt, c1);
        cudaEventRecord(evH1[t], s2);
    }

    // ---- main chain: lstm2 -> q -> att_e -> att_av -> comb (7 launches/step) ----
    int cur = 0;
    for (int t = 0; t < Tsz; t++) {
        int nxt = cur ^ 1;
        float* h1nxt = h1all + (size_t)(t + 1) * Bsz * Hsz;
        cudaStreamWaitEvent(0, evH1[t], 0);
        // LSTM2: [h1 | o | h2] ; K=3072, KSPLIT 8 (6 tiles/CTA, 256 CTAs = 1 wave)
        hmma_kernel<<<dim3(32, 8), 256, 49152>>>(
            h1nxt, Hsz, 1024, o, Hsz, 1024, h2p[cur], Hsz,
            b2h, b2l, 3072, 4096, 384, 0, part);
        lstm_reduce<<<256, 256>>>(part, 8, b_ih2, b_hh2, h2p[nxt], c2);
        // q = h2 @ W_att ; K=1024, KSPLIT 16 (1 tile/CTA, 128 CTAs)
        hmma_kernel<<<dim3(8, 16), 256, 49152>>>(
            h2p[nxt], Hsz, 1024, nullptr, 0, 0, nullptr, 0,
            bqh, bql, 1024, 1024, 64, 0, part);
        // attention: e-dots (256 CTAs, q summed inline), then softmax+weighted sum (256 CTAs)
        att_e_kernel<<<dim3(4, 64), 256>>>(part, 16, enc, e);
        att_av_kernel<<<dim3(4, 64), 256>>>(e, masks, enc, at);
        // o_t = tanh([a_t | h2] @ W_comb^T + b_comb) ; K=2048, KSPLIT 16 (2 tiles/CTA, 128 CTAs)
        hmma_kernel<<<dim3(8, 16), 256, 49152>>>(
            at, Hsz, 1024, h2p[nxt], Hsz, 1024, nullptr, 0,
            bch, bcl, 2048, 1024, 128, 0, part);
        tanh_reduce<<<64, 256>>>(part, 16, b_comb, o, out + (size_t)t * Bsz * Hsz);
        cur = nxt;
    }
}